// round 8
// baseline (speedup 1.0000x reference)
#include <cuda_runtime.h>
#include <cstdint>

// CrfHead: out[b,t,:] = x[b,t,:] + transitions[argmax(x[b,t,:]), :]
// 131072 rows x 256 floats.
// Persistent grid (one wave, 1216 CTAs) + prefetch.global.L2 of the next
// grid-stride row: DRAM fetch for row i+T flies during row i's compute/gather
// tail with zero register or scoreboard cost. Cache split from R7:
//   x -> __ldcg (L2 only), transitions -> __ldg (L1-resident), out -> __stcs.

#define TAGS 256
#define ROWS (128 * 1024)
#define THREADS 256
#define NBLOCKS 1216                       // 152 SMs x 8 resident CTAs
#define TOTAL_WARPS (NBLOCKS * THREADS / 32)   // 9728
#define F4_PER_ROW (TAGS / 4)              // 64

__device__ __forceinline__ void prefetch_l2(const float4* p) {
    asm volatile("prefetch.global.L2 [%0];" :: "l"(p));
}

// Monotone float -> uint32 map (total order matches float <; no NaNs in input).
__device__ __forceinline__ unsigned ford(float f) {
    unsigned u = __float_as_uint(f);
    return (u >> 31) ? ~u : (u | 0x80000000u);
}

__global__ __launch_bounds__(THREADS, 8)
void crf_head_kernel(const float4* __restrict__ x,
                     const float* __restrict__ trans,
                     float4* __restrict__ out) {
    const int gwarp = (blockIdx.x * THREADS + threadIdx.x) >> 5;
    const int lane  = threadIdx.x & 31;

    for (int row = gwarp; row < ROWS; row += TOTAL_WARPS) {
        const size_t base = (size_t)row * F4_PER_ROW;

        // Prefetch next iteration's row into L2 (async, no reg/scoreboard cost).
        const int nrow = row + TOTAL_WARPS;
        if (nrow < ROWS) {
            const size_t nb = (size_t)nrow * F4_PER_ROW;
            prefetch_l2(&x[nb + lane]);
            prefetch_l2(&x[nb + lane + 32]);
        }

        // Streaming reads: L2-only so L1 stays reserved for transitions.
        const float4 a = __ldcg(&x[base + lane]);
        const float4 b = __ldcg(&x[base + lane + 32]);

        // Lane-local argmax over 8 elems; strict > keeps lowest index.
        const int i0 = lane * 4, i1 = (lane + 32) * 4;
        float v = a.x; int idx = i0;
        if (a.y > v) { v = a.y; idx = i0 + 1; }
        if (a.z > v) { v = a.z; idx = i0 + 2; }
        if (a.w > v) { v = a.w; idx = i0 + 3; }
        if (b.x > v) { v = b.x; idx = i1;     }
        if (b.y > v) { v = b.y; idx = i1 + 1; }
        if (b.z > v) { v = b.z; idx = i1 + 2; }
        if (b.w > v) { v = b.w; idx = i1 + 3; }

        // Warp argmax: REDUX.MAX on ordered key, REDUX.MIN on candidate index
        // (exact first-occurrence tie-break; lanes own disjoint index sets).
        const unsigned k = ford(v);
        const unsigned m = __reduce_max_sync(0xFFFFFFFFu, k);
        const unsigned cand = (k == m) ? (unsigned)idx : 0xFFFFu;
        const int best = (int)__reduce_min_sync(0xFFFFFFFFu, cand);

        // transitions row: 256KB working set, L1-resident (ld.global.nc).
        const float4* trow = reinterpret_cast<const float4*>(trans + (size_t)best * TAGS);
        const float4 t0 = __ldg(&trow[lane]);
        const float4 t1 = __ldg(&trow[lane + 32]);

        float4 r;
        r.x = a.x + t0.x; r.y = a.y + t0.y; r.z = a.z + t0.z; r.w = a.w + t0.w;
        __stcs(&out[base + lane], r);
        r.x = b.x + t1.x; r.y = b.y + t1.y; r.z = b.z + t1.z; r.w = b.w + t1.w;
        __stcs(&out[base + lane + 32], r);
    }
}

extern "C" void kernel_launch(void* const* d_in, const int* in_sizes, int n_in,
                              void* d_out, int out_size) {
    const float4* x     = reinterpret_cast<const float4*>(d_in[0]);
    const float*  trans = reinterpret_cast<const float*>(d_in[1]);
    float4*       out   = reinterpret_cast<float4*>(d_out);

    crf_head_kernel<<<NBLOCKS, THREADS>>>(x, trans, out);
}

// round 9
// speedup vs baseline: 1.1001x; 1.1001x over previous
#include <cuda_runtime.h>
#include <cstdint>

// CrfHead: out[b,t,:] = x[b,t,:] + transitions[argmax(x[b,t,:]), :]
// 131072 rows x 256 floats.
// Two-phase batch (K=4 rows/warp):
//  Phase 1: load rows (DRAM, high MLP — row data dies into argmax, so loads
//           pipeline across rows without register cost), save best[j].
//  Phase 2: re-load rows via __ldcg (L2 HIT: chip-wide hot set ~39MB < 126MB
//           L2, reuse distance ~2us) + __ldg transitions (L1-resident),
//           add, __stcs store. Pure drain, no DRAM reads.
// This decouples DRAM-read MLP from register lifetime: ~64 warps/SM with
// 4-8 outstanding lines during phase 1 -> first config above the ~16KB/SM
// latency-bandwidth product.

#define TAGS 256
#define ROWS (128 * 1024)
#define THREADS 256
#define K 4                                    // rows per warp
#define ROWS_PER_BLOCK ((THREADS / 32) * K)    // 32
#define BLOCKS (ROWS / ROWS_PER_BLOCK)         // 4096
#define F4_PER_ROW (TAGS / 4)                  // 64

// Monotone float -> uint32 map (total order matches float <; no NaNs in input).
__device__ __forceinline__ unsigned ford(float f) {
    unsigned u = __float_as_uint(f);
    return (u >> 31) ? ~u : (u | 0x80000000u);
}

__global__ __launch_bounds__(THREADS)
void crf_head_kernel(const float4* __restrict__ x,
                     const float* __restrict__ trans,
                     float4* __restrict__ out) {
    const int warp = (blockIdx.x * THREADS + threadIdx.x) >> 5;
    const int lane = threadIdx.x & 31;

    const size_t base = (size_t)warp * K * F4_PER_ROW;

    int best[K];

    // ---- Phase 1: argmax of K rows. Row data is consumed immediately, so
    // ptxas can keep several rows' loads in flight concurrently. ----
    #pragma unroll
    for (int j = 0; j < K; j++) {
        const size_t rb = base + (size_t)j * F4_PER_ROW;
        const float4 a = __ldcg(&x[rb + lane]);
        const float4 b = __ldcg(&x[rb + lane + 32]);

        const int i0 = lane * 4, i1 = (lane + 32) * 4;
        float v = a.x; int idx = i0;
        if (a.y > v) { v = a.y; idx = i0 + 1; }
        if (a.z > v) { v = a.z; idx = i0 + 2; }
        if (a.w > v) { v = a.w; idx = i0 + 3; }
        if (b.x > v) { v = b.x; idx = i1;     }
        if (b.y > v) { v = b.y; idx = i1 + 1; }
        if (b.z > v) { v = b.z; idx = i1 + 2; }
        if (b.w > v) { v = b.w; idx = i1 + 3; }

        // REDUX.MAX on ordered key, REDUX.MIN on candidate index
        // (exact first-occurrence tie-break; lanes own disjoint index sets).
        const unsigned kk = ford(v);
        const unsigned mm = __reduce_max_sync(0xFFFFFFFFu, kk);
        const unsigned cand = (kk == mm) ? (unsigned)idx : 0xFFFFu;
        best[j] = (int)__reduce_min_sync(0xFFFFFFFFu, cand);
    }

    // ---- Phase 2: re-read rows (L2 hits) + transitions (L1), add, store. ----
    #pragma unroll
    for (int j = 0; j < K; j++) {
        const size_t rb = base + (size_t)j * F4_PER_ROW;
        const float4 a = __ldcg(&x[rb + lane]);
        const float4 b = __ldcg(&x[rb + lane + 32]);

        const float4* trow =
            reinterpret_cast<const float4*>(trans + (size_t)best[j] * TAGS);
        const float4 t0 = __ldg(&trow[lane]);
        const float4 t1 = __ldg(&trow[lane + 32]);

        float4 r;
        r.x = a.x + t0.x; r.y = a.y + t0.y; r.z = a.z + t0.z; r.w = a.w + t0.w;
        __stcs(&out[rb + lane], r);
        r.x = b.x + t1.x; r.y = b.y + t1.y; r.z = b.z + t1.z; r.w = b.w + t1.w;
        __stcs(&out[rb + lane + 32], r);
    }
}

extern "C" void kernel_launch(void* const* d_in, const int* in_sizes, int n_in,
                              void* d_out, int out_size) {
    const float4* x     = reinterpret_cast<const float4*>(d_in[0]);
    const float*  trans = reinterpret_cast<const float*>(d_in[1]);
    float4*       out   = reinterpret_cast<float4*>(d_out);

    crf_head_kernel<<<BLOCKS, THREADS>>>(x, trans, out);
}

// round 13
// speedup vs baseline: 1.1479x; 1.0434x over previous
#include <cuda_runtime.h>
#include <cstdint>

// CrfHead: out[b,t,:] = x[b,t,:] + transitions[argmax(x[b,t,:]), :]
// 131072 rows x 256 floats. R7 shape (1 row/warp, cache split) upgraded to
// Blackwell 256-bit vector memory ops: ONE ld.global.cg.v8.f32 per lane
// covers the whole row (32 lanes x 8 floats = 256), one v8 nc load for the
// L1-resident transitions row, one v8 .cs store. Halves LDG/STG count and
// issue-phase length vs 128-bit pairs; regs stay low -> full occupancy.

#define TAGS 256
#define ROWS (128 * 1024)
#define THREADS 256
#define WARPS_PER_BLOCK (THREADS / 32)
#define BLOCKS (ROWS / WARPS_PER_BLOCK)   // 16384

// Monotone float -> uint32 map (total order matches float <; no NaNs in input).
__device__ __forceinline__ unsigned ford(float f) {
    unsigned u = __float_as_uint(f);
    return (u >> 31) ? ~u : (u | 0x80000000u);
}

__device__ __forceinline__ void ldg_cg_v8(const float* p, float* v) {
    asm volatile("ld.global.cg.v8.f32 {%0,%1,%2,%3,%4,%5,%6,%7}, [%8];"
                 : "=f"(v[0]), "=f"(v[1]), "=f"(v[2]), "=f"(v[3]),
                   "=f"(v[4]), "=f"(v[5]), "=f"(v[6]), "=f"(v[7])
                 : "l"(p));
}

__device__ __forceinline__ void ldg_nc_v8(const float* p, float* v) {
    asm volatile("ld.global.nc.v8.f32 {%0,%1,%2,%3,%4,%5,%6,%7}, [%8];"
                 : "=f"(v[0]), "=f"(v[1]), "=f"(v[2]), "=f"(v[3]),
                   "=f"(v[4]), "=f"(v[5]), "=f"(v[6]), "=f"(v[7])
                 : "l"(p));
}

__device__ __forceinline__ void stg_cs_v8(float* p, const float* v) {
    asm volatile("st.global.cs.v8.f32 [%0], {%1,%2,%3,%4,%5,%6,%7,%8};"
                 :: "l"(p),
                    "f"(v[0]), "f"(v[1]), "f"(v[2]), "f"(v[3]),
                    "f"(v[4]), "f"(v[5]), "f"(v[6]), "f"(v[7])
                 : "memory");
}

__global__ __launch_bounds__(THREADS, 8)
void crf_head_kernel(const float* __restrict__ x,
                     const float* __restrict__ trans,
                     float* __restrict__ out) {
    const int warp = (blockIdx.x * THREADS + threadIdx.x) >> 5;
    const int lane = threadIdx.x & 31;

    // Lane owns 8 contiguous elements: [lane*8, lane*8+8).
    const size_t base = (size_t)warp * TAGS + lane * 8;

    float a[8];
    ldg_cg_v8(&x[base], a);   // single 256-bit streaming load (L2 only)

    // Lane-local argmax; strict > keeps lowest index.
    const int i0 = lane * 8;
    float v = a[0]; int idx = i0;
    #pragma unroll
    for (int e = 1; e < 8; e++)
        if (a[e] > v) { v = a[e]; idx = i0 + e; }

    // Warp argmax: REDUX.MAX on ordered key, REDUX.MIN on candidate index
    // (exact first-occurrence tie-break; lanes own disjoint ordered ranges).
    const unsigned k = ford(v);
    const unsigned m = __reduce_max_sync(0xFFFFFFFFu, k);
    const unsigned cand = (k == m) ? (unsigned)idx : 0xFFFFu;
    const int best = (int)__reduce_min_sync(0xFFFFFFFFu, cand);

    // transitions row: 256KB working set, L1-resident via nc path.
    float t[8];
    ldg_nc_v8(&trans[(size_t)best * TAGS + lane * 8], t);

    float r[8];
    #pragma unroll
    for (int e = 0; e < 8; e++) r[e] = a[e] + t[e];

    stg_cs_v8(&out[base], r); // single 256-bit streaming store
}

extern "C" void kernel_launch(void* const* d_in, const int* in_sizes, int n_in,
                              void* d_out, int out_size) {
    const float* x     = reinterpret_cast<const float*>(d_in[0]);
    const float* trans = reinterpret_cast<const float*>(d_in[1]);
    float*       out   = reinterpret_cast<float*>(d_out);

    crf_head_kernel<<<BLOCKS, THREADS>>>(x, trans, out);
}